// round 1
// baseline (speedup 1.0000x reference)
#include <cuda_runtime.h>
#include <math.h>

#define SS    128
#define LFREQ 10

__device__ float g_dt;

typedef unsigned long long u64;

__device__ __forceinline__ u64 pack2(float lo, float hi) {
    u64 r; asm("mov.b64 %0, {%1,%2};" : "=l"(r) : "f"(lo), "f"(hi)); return r;
}
__device__ __forceinline__ void unpack2(u64 v, float& lo, float& hi) {
    asm("mov.b64 {%0,%1}, %2;" : "=f"(lo), "=f"(hi) : "l"(v));
}
__device__ __forceinline__ u64 fma2(u64 a, u64 b, u64 c) {
    u64 d; asm("fma.rn.f32x2 %0, %1, %2, %3;" : "=l"(d) : "l"(a), "l"(b), "l"(c)); return d;
}

// Shared-memory float offsets (all even -> 8B aligned for f32x2 loads)
#define OFF_W1   0      // 63*64 = 4032
#define OFF_W2   4032   // 64*64 = 4096
#define OFF_WO   8128   // 64*18 = 1152 (17 cols + zero pad)
#define OFF_B1   9280   // 64
#define OFF_B2   9344   // 64
#define OFF_BO   9408   // 18 (17 + pad)
#define OFF_WRGB 9426   // 48
#define OFF_BRGB 9474   // 3
#define SM_TOT   9477

__device__ __forceinline__ void apply_row64(u64* acc, const float* srow, float e) {
    u64 e2 = pack2(e, e);
    const u64* wr = reinterpret_cast<const u64*>(srow);
#pragma unroll
    for (int j = 0; j < 32; j++) acc[j] = fma2(e2, wr[j], acc[j]);
}

__device__ __forceinline__ void apply_row18(u64* acc, const float* srow, float e) {
    u64 e2 = pack2(e, e);
    const u64* wr = reinterpret_cast<const u64*>(srow);
#pragma unroll
    for (int j = 0; j < 9; j++) acc[j] = fma2(e2, wr[j], acc[j]);
}

__global__ void dt_kernel(const float* __restrict__ tmin,
                          const float* __restrict__ tmax, int n) {
    __shared__ float red[256];
    int tid = threadIdx.x;
    float acc = 0.f;
    for (int i = tid; i < n; i += 256) acc += tmax[i] - tmin[i];
    red[tid] = acc;
    __syncthreads();
    for (int s = 128; s > 0; s >>= 1) {
        if (tid < s) red[tid] += red[tid + s];
        __syncthreads();
    }
    if (tid == 0) g_dt = (red[0] / (float)n) / (float)SS;
}

__global__ void __launch_bounds__(128)
nerf_kernel(const float* __restrict__ ox, const float* __restrict__ oy,
            const float* __restrict__ oz, const float* __restrict__ dxv,
            const float* __restrict__ dyv, const float* __restrict__ dzv,
            const float* __restrict__ tmin, const float* __restrict__ tmax,
            const float* __restrict__ W1, const float* __restrict__ b1,
            const float* __restrict__ W2, const float* __restrict__ b2,
            const float* __restrict__ Wo, const float* __restrict__ bo,
            const float* __restrict__ Wrgb, const float* __restrict__ brgb,
            float* __restrict__ out, int n)
{
    __shared__ __align__(16) float sm[SM_TOT];
    const int tid = threadIdx.x;

    // --- stage weights in shared ---
    for (int i = tid; i < 4032; i += 128) sm[OFF_W1 + i] = W1[i];
    for (int i = tid; i < 4096; i += 128) sm[OFF_W2 + i] = W2[i];
    for (int i = tid; i < 1152; i += 128) {
        int r = i / 18, c = i % 18;
        sm[OFF_WO + i] = (c < 17) ? Wo[r * 17 + c] : 0.f;
    }
    for (int i = tid; i < 64; i += 128) sm[OFF_B1 + i] = b1[i];
    for (int i = tid; i < 64; i += 128) sm[OFF_B2 + i] = b2[i];
    for (int i = tid; i < 18; i += 128) sm[OFF_BO + i] = (i < 17) ? bo[i] : 0.f;
    for (int i = tid; i < 48; i += 128) sm[OFF_WRGB + i] = Wrgb[i];
    for (int i = tid; i < 3;  i += 128) sm[OFF_BRGB + i] = brgb[i];
    __syncthreads();

    const int ray = blockIdx.x;
    const float tmn = tmin[ray], tmx = tmax[ray];
    const float t  = fmaf((float)tid * (1.0f / (float)(SS - 1)), tmx - tmn, tmn);
    const float px = fmaf(dxv[ray], t, ox[ray]);
    const float py = fmaf(dyv[ray], t, oy[ray]);
    const float pz = fmaf(dzv[ray], t, oz[ray]);

    // ---------- layer 1: enc(63) @ W1 + b1, enc streamed ----------
    u64 acc1[32];
#pragma unroll
    for (int j = 0; j < 32; j++) acc1[j] = *reinterpret_cast<const u64*>(&sm[OFF_B1 + 2 * j]);

    apply_row64(acc1, &sm[OFF_W1 + 0 * 64], px);
    apply_row64(acc1, &sm[OFF_W1 + 1 * 64], py);
    apply_row64(acc1, &sm[OFF_W1 + 2 * 64], pz);

    float pc0 = px, pc1 = py, pc2 = pz;
#pragma unroll 1
    for (int c = 0; c < 3; c++) {
        float base = (c == 0) ? pc0 : ((c == 1) ? pc1 : pc2);
        float sv, cv;
        sincosf(base, &sv, &cv);
#pragma unroll 1
        for (int f = 0; f < LFREQ; f++) {
            apply_row64(acc1, &sm[OFF_W1 + (3 + 20 * c + f) * 64], sv);
            apply_row64(acc1, &sm[OFF_W1 + (3 + 20 * c + 10 + f) * 64], cv);
            // angle doubling: (s,c) -> (2sc, c^2 - s^2)
            float ns = 2.0f * sv * cv;
            float nc = fmaf(cv, cv, -(sv * sv));
            sv = ns; cv = nc;
        }
    }

    // ---------- layer 2: relu(h1) @ W2 + b2 ----------
    u64 acc2[32];
#pragma unroll
    for (int j = 0; j < 32; j++) acc2[j] = *reinterpret_cast<const u64*>(&sm[OFF_B2 + 2 * j]);
#pragma unroll 1
    for (int k = 0; k < 32; k++) {
        float e0, e1; unpack2(acc1[k], e0, e1);
        e0 = fmaxf(e0, 0.f); e1 = fmaxf(e1, 0.f);
        apply_row64(acc2, &sm[OFF_W2 + (2 * k) * 64], e0);
        apply_row64(acc2, &sm[OFF_W2 + (2 * k + 1) * 64], e1);
    }

    // ---------- layer 3: relu(h2) @ W_out + b_out (17 padded to 18) ----------
    u64 acco[9];
#pragma unroll
    for (int j = 0; j < 9; j++) acco[j] = *reinterpret_cast<const u64*>(&sm[OFF_BO + 2 * j]);
#pragma unroll 1
    for (int k = 0; k < 32; k++) {
        float e0, e1; unpack2(acc2[k], e0, e1);
        e0 = fmaxf(e0, 0.f); e1 = fmaxf(e1, 0.f);
        apply_row18(acco, &sm[OFF_WO + (2 * k) * 18], e0);
        apply_row18(acco, &sm[OFF_WO + (2 * k + 1) * 18], e1);
    }
    float o[18];
#pragma unroll
    for (int j = 0; j < 9; j++) unpack2(acco[j], o[2 * j], o[2 * j + 1]);

    const float sigma = fmaxf(o[0], 0.f);

    // rgb head: sigmoid(feat(16) @ W_rgb + b_rgb)
    float rgbv[3];
#pragma unroll
    for (int cc = 0; cc < 3; cc++) {
        float r = sm[OFF_BRGB + cc];
#pragma unroll
        for (int k = 0; k < 16; k++) r = fmaf(o[1 + k], sm[OFF_WRGB + k * 3 + cc], r);
        rgbv[cc] = 1.0f / (1.0f + expf(-r));
    }

    // ---------- volume rendering ----------
    const float dtv   = g_dt;
    const float ee    = expf(-sigma * dtv);
    const float alpha = 1.0f - ee;
    const float q     = (1.0f - alpha) + 1e-10f;

    const int lane = tid & 31, wp = tid >> 5;
    float p = q;
#pragma unroll
    for (int d = 1; d < 32; d <<= 1) {
        float u = __shfl_up_sync(0xffffffffu, p, d);
        if (lane >= d) p *= u;
    }
    __shared__ float wtot[4];
    if (lane == 31) wtot[wp] = p;
    __syncthreads();
    float pre = 1.0f;
    for (int w = 0; w < wp; w++) pre *= wtot[w];
    float excl = __shfl_up_sync(0xffffffffu, p, 1);
    if (lane == 0) excl = 1.0f;
    const float T    = pre * excl;          // exclusive transmittance
    const float incl = pre * p;             // inclusive cumprod
    const float wgt  = (T > 1e-4f) ? (T * alpha) : 0.f;

    float v0 = wgt * rgbv[0], v1 = wgt * rgbv[1], v2 = wgt * rgbv[2];
#pragma unroll
    for (int off = 16; off > 0; off >>= 1) {
        v0 += __shfl_down_sync(0xffffffffu, v0, off);
        v1 += __shfl_down_sync(0xffffffffu, v1, off);
        v2 += __shfl_down_sync(0xffffffffu, v2, off);
    }
    __shared__ float redc[4][3];
    if (lane == 0) { redc[wp][0] = v0; redc[wp][1] = v1; redc[wp][2] = v2; }
    if (tid == SS - 1) out[3 * n + ray] = incl;   // T_out
    __syncthreads();
    if (tid == 0) {
        out[ray * 3 + 0] = redc[0][0] + redc[1][0] + redc[2][0] + redc[3][0];
        out[ray * 3 + 1] = redc[0][1] + redc[1][1] + redc[2][1] + redc[3][1];
        out[ray * 3 + 2] = redc[0][2] + redc[1][2] + redc[2][2] + redc[3][2];
    }
}

extern "C" void kernel_launch(void* const* d_in, const int* in_sizes, int n_in,
                              void* d_out, int out_size) {
    const float* ox   = (const float*)d_in[0];
    const float* oy   = (const float*)d_in[1];
    const float* oz   = (const float*)d_in[2];
    const float* dxv  = (const float*)d_in[3];
    const float* dyv  = (const float*)d_in[4];
    const float* dzv  = (const float*)d_in[5];
    const float* tmin = (const float*)d_in[6];
    const float* tmax = (const float*)d_in[7];
    const float* W1   = (const float*)d_in[8];
    const float* b1   = (const float*)d_in[9];
    const float* W2   = (const float*)d_in[10];
    const float* b2   = (const float*)d_in[11];
    const float* Wo   = (const float*)d_in[12];
    const float* bo   = (const float*)d_in[13];
    const float* Wrgb = (const float*)d_in[14];
    const float* brgb = (const float*)d_in[15];
    float* out = (float*)d_out;
    const int n = in_sizes[0];

    dt_kernel<<<1, 256>>>(tmin, tmax, n);
    nerf_kernel<<<n, 128>>>(ox, oy, oz, dxv, dyv, dzv, tmin, tmax,
                            W1, b1, W2, b2, Wo, bo, Wrgb, brgb, out, n);
}

// round 2
// speedup vs baseline: 1.5397x; 1.5397x over previous
#include <cuda_runtime.h>
#include <math.h>

#define SS    128
#define LFREQ 10

__device__ float g_dt;

typedef unsigned long long u64;

__device__ __forceinline__ u64 pack2(float lo, float hi) {
    u64 r; asm("mov.b64 %0, {%1,%2};" : "=l"(r) : "f"(lo), "f"(hi)); return r;
}
__device__ __forceinline__ void unpack2(u64 v, float& lo, float& hi) {
    asm("mov.b64 {%0,%1}, %2;" : "=f"(lo), "=f"(hi) : "l"(v));
}
__device__ __forceinline__ u64 fma2(u64 a, u64 b, u64 c) {
    u64 d; asm("fma.rn.f32x2 %0, %1, %2, %3;" : "=l"(d) : "l"(a), "l"(b), "l"(c)); return d;
}

// Shared-memory float offsets (all 4-float aligned -> 16B aligned rows)
#define OFF_W1   0      // 63*64  = 4032
#define OFF_W2   4032   // 64*64  = 4096
#define OFF_WO   8128   // 64*20  = 1280 (17 cols zero-padded to 20)
#define OFF_B1   9408   // 64
#define OFF_B2   9472   // 64
#define OFF_BO   9536   // 20
#define OFF_WRGB 9556   // 48
#define OFF_BRGB 9604   // 3
#define SM_TOT   9608

__device__ __forceinline__ void apply_row64(u64* acc, const float* srow, float e) {
    u64 e2 = pack2(e, e);
    const ulonglong2* wr = reinterpret_cast<const ulonglong2*>(srow);
#pragma unroll
    for (int j = 0; j < 16; j++) {
        ulonglong2 v = wr[j];
        acc[2 * j]     = fma2(e2, v.x, acc[2 * j]);
        acc[2 * j + 1] = fma2(e2, v.y, acc[2 * j + 1]);
    }
}

__device__ __forceinline__ void apply_row20(u64* acc, const float* srow, float e) {
    u64 e2 = pack2(e, e);
    const ulonglong2* wr = reinterpret_cast<const ulonglong2*>(srow);
#pragma unroll
    for (int j = 0; j < 5; j++) {
        ulonglong2 v = wr[j];
        acc[2 * j]     = fma2(e2, v.x, acc[2 * j]);
        acc[2 * j + 1] = fma2(e2, v.y, acc[2 * j + 1]);
    }
}

__global__ void dt_kernel(const float* __restrict__ tmin,
                          const float* __restrict__ tmax, int n) {
    __shared__ float red[256];
    int tid = threadIdx.x;
    float acc = 0.f;
    for (int i = tid; i < n; i += 256) acc += tmax[i] - tmin[i];
    red[tid] = acc;
    __syncthreads();
    for (int s = 128; s > 0; s >>= 1) {
        if (tid < s) red[tid] += red[tid + s];
        __syncthreads();
    }
    if (tid == 0) g_dt = (red[0] / (float)n) / (float)SS;
}

#define TPB 512
#define RAYS_PER_CTA 4

__global__ void __launch_bounds__(TPB)
nerf_kernel(const float* __restrict__ ox, const float* __restrict__ oy,
            const float* __restrict__ oz, const float* __restrict__ dxv,
            const float* __restrict__ dyv, const float* __restrict__ dzv,
            const float* __restrict__ tmin, const float* __restrict__ tmax,
            const float* __restrict__ W1, const float* __restrict__ b1,
            const float* __restrict__ W2, const float* __restrict__ b2,
            const float* __restrict__ Wo, const float* __restrict__ bo,
            const float* __restrict__ Wrgb, const float* __restrict__ brgb,
            float* __restrict__ out, int n)
{
    __shared__ __align__(16) float sm[SM_TOT];
    const int tid = threadIdx.x;

    // --- stage weights in shared ---
    for (int i = tid; i < 4032; i += TPB) sm[OFF_W1 + i] = W1[i];
    for (int i = tid; i < 4096; i += TPB) sm[OFF_W2 + i] = W2[i];
    for (int i = tid; i < 1280; i += TPB) {
        int r = i / 20, c = i % 20;
        sm[OFF_WO + i] = (c < 17) ? Wo[r * 17 + c] : 0.f;
    }
    for (int i = tid; i < 64; i += TPB) sm[OFF_B1 + i] = b1[i];
    for (int i = tid; i < 64; i += TPB) sm[OFF_B2 + i] = b2[i];
    for (int i = tid; i < 20; i += TPB) sm[OFF_BO + i] = (i < 17) ? bo[i] : 0.f;
    for (int i = tid; i < 48; i += TPB) sm[OFF_WRGB + i] = Wrgb[i];
    for (int i = tid; i < 3;  i += TPB) sm[OFF_BRGB + i] = brgb[i];
    __syncthreads();

    const int grp  = tid >> 7;          // 0..3: which ray within CTA
    const int gtid = tid & 127;         // sample index within ray
    const int ray  = blockIdx.x * RAYS_PER_CTA + grp;

    const float tmn = tmin[ray], tmx = tmax[ray];
    const float t  = fmaf((float)gtid * (1.0f / (float)(SS - 1)), tmx - tmn, tmn);
    const float px = fmaf(dxv[ray], t, ox[ray]);
    const float py = fmaf(dyv[ray], t, oy[ray]);
    const float pz = fmaf(dzv[ray], t, oz[ray]);

    // ---------- layer 1: enc(63) @ W1 + b1, enc streamed ----------
    u64 acc1[32];
#pragma unroll
    for (int j = 0; j < 32; j++) acc1[j] = *reinterpret_cast<const u64*>(&sm[OFF_B1 + 2 * j]);

    apply_row64(acc1, &sm[OFF_W1 + 0 * 64], px);
    apply_row64(acc1, &sm[OFF_W1 + 1 * 64], py);
    apply_row64(acc1, &sm[OFF_W1 + 2 * 64], pz);

#pragma unroll 1
    for (int c = 0; c < 3; c++) {
        float base = (c == 0) ? px : ((c == 1) ? py : pz);
        float sv, cv;
        sincosf(base, &sv, &cv);
#pragma unroll 1
        for (int f = 0; f < LFREQ; f++) {
            apply_row64(acc1, &sm[OFF_W1 + (3 + 20 * c + f) * 64], sv);
            apply_row64(acc1, &sm[OFF_W1 + (3 + 20 * c + 10 + f) * 64], cv);
            float ns = 2.0f * sv * cv;
            float nc = fmaf(cv, cv, -(sv * sv));
            sv = ns; cv = nc;
        }
    }

    // ---------- layer 2: relu(h1) @ W2 + b2 ----------
    u64 acc2[32];
#pragma unroll
    for (int j = 0; j < 32; j++) acc2[j] = *reinterpret_cast<const u64*>(&sm[OFF_B2 + 2 * j]);
#pragma unroll 1
    for (int k = 0; k < 32; k++) {
        float e0, e1; unpack2(acc1[k], e0, e1);
        e0 = fmaxf(e0, 0.f); e1 = fmaxf(e1, 0.f);
        apply_row64(acc2, &sm[OFF_W2 + (2 * k) * 64], e0);
        apply_row64(acc2, &sm[OFF_W2 + (2 * k + 1) * 64], e1);
    }

    // ---------- layer 3: relu(h2) @ W_out + b_out (17 padded to 20) ----------
    u64 acco[10];
#pragma unroll
    for (int j = 0; j < 10; j++) acco[j] = *reinterpret_cast<const u64*>(&sm[OFF_BO + 2 * j]);
#pragma unroll 1
    for (int k = 0; k < 32; k++) {
        float e0, e1; unpack2(acc2[k], e0, e1);
        e0 = fmaxf(e0, 0.f); e1 = fmaxf(e1, 0.f);
        apply_row20(acco, &sm[OFF_WO + (2 * k) * 20], e0);
        apply_row20(acco, &sm[OFF_WO + (2 * k + 1) * 20], e1);
    }
    float o[20];
#pragma unroll
    for (int j = 0; j < 10; j++) unpack2(acco[j], o[2 * j], o[2 * j + 1]);

    const float sigma = fmaxf(o[0], 0.f);

    // rgb head: sigmoid(feat(16) @ W_rgb + b_rgb)
    float rgbv[3];
#pragma unroll
    for (int cc = 0; cc < 3; cc++) {
        float r = sm[OFF_BRGB + cc];
#pragma unroll
        for (int k = 0; k < 16; k++) r = fmaf(o[1 + k], sm[OFF_WRGB + k * 3 + cc], r);
        rgbv[cc] = 1.0f / (1.0f + expf(-r));
    }

    // ---------- volume rendering ----------
    const float dtv   = g_dt;
    const float ee    = expf(-sigma * dtv);
    const float alpha = 1.0f - ee;
    const float q     = (1.0f - alpha) + 1e-10f;

    const int lane = gtid & 31, wp = gtid >> 5;
    float p = q;
#pragma unroll
    for (int d = 1; d < 32; d <<= 1) {
        float u = __shfl_up_sync(0xffffffffu, p, d);
        if (lane >= d) p *= u;
    }
    __shared__ float wtot[RAYS_PER_CTA][4];
    if (lane == 31) wtot[grp][wp] = p;
    __syncthreads();
    float pre = 1.0f;
    for (int w = 0; w < wp; w++) pre *= wtot[grp][w];
    float excl = __shfl_up_sync(0xffffffffu, p, 1);
    if (lane == 0) excl = 1.0f;
    const float T    = pre * excl;          // exclusive transmittance
    const float incl = pre * p;             // inclusive cumprod
    const float wgt  = (T > 1e-4f) ? (T * alpha) : 0.f;

    float v0 = wgt * rgbv[0], v1 = wgt * rgbv[1], v2 = wgt * rgbv[2];
#pragma unroll
    for (int off = 16; off > 0; off >>= 1) {
        v0 += __shfl_down_sync(0xffffffffu, v0, off);
        v1 += __shfl_down_sync(0xffffffffu, v1, off);
        v2 += __shfl_down_sync(0xffffffffu, v2, off);
    }
    __shared__ float redc[RAYS_PER_CTA][4][3];
    if (lane == 0) { redc[grp][wp][0] = v0; redc[grp][wp][1] = v1; redc[grp][wp][2] = v2; }
    if (gtid == SS - 1) out[3 * n + ray] = incl;   // T_out
    __syncthreads();
    if (gtid == 0) {
        out[ray * 3 + 0] = redc[grp][0][0] + redc[grp][1][0] + redc[grp][2][0] + redc[grp][3][0];
        out[ray * 3 + 1] = redc[grp][0][1] + redc[grp][1][1] + redc[grp][2][1] + redc[grp][3][1];
        out[ray * 3 + 2] = redc[grp][0][2] + redc[grp][1][2] + redc[grp][2][2] + redc[grp][3][2];
    }
}

extern "C" void kernel_launch(void* const* d_in, const int* in_sizes, int n_in,
                              void* d_out, int out_size) {
    const float* ox   = (const float*)d_in[0];
    const float* oy   = (const float*)d_in[1];
    const float* oz   = (const float*)d_in[2];
    const float* dxv  = (const float*)d_in[3];
    const float* dyv  = (const float*)d_in[4];
    const float* dzv  = (const float*)d_in[5];
    const float* tmin = (const float*)d_in[6];
    const float* tmax = (const float*)d_in[7];
    const float* W1   = (const float*)d_in[8];
    const float* b1   = (const float*)d_in[9];
    const float* W2   = (const float*)d_in[10];
    const float* b2   = (const float*)d_in[11];
    const float* Wo   = (const float*)d_in[12];
    const float* bo   = (const float*)d_in[13];
    const float* Wrgb = (const float*)d_in[14];
    const float* brgb = (const float*)d_in[15];
    float* out = (float*)d_out;
    const int n = in_sizes[0];

    dt_kernel<<<1, 256>>>(tmin, tmax, n);
    nerf_kernel<<<n / RAYS_PER_CTA, TPB>>>(ox, oy, oz, dxv, dyv, dzv, tmin, tmax,
                                           W1, b1, W2, b2, Wo, bo, Wrgb, brgb, out, n);
}

// round 4
// speedup vs baseline: 1.8613x; 1.2089x over previous
#include <cuda_runtime.h>
#include <cuda_bf16.h>
#include <cstdint>
#include <math.h>

#define SS    128
#define LFREQ 10

__device__ float g_dt;

// ---------------- helpers ----------------
__device__ __forceinline__ uint32_t smem_to_u32(const void* p) {
    uint32_t a;
    asm("{ .reg .u64 t; cvta.to.shared.u64 t, %1; cvt.u32.u64 %0, t; }" : "=r"(a) : "l"(p));
    return a;
}

__device__ __forceinline__ void ldsm4(uint32_t* r, uint32_t addr) {
    asm volatile("ldmatrix.sync.aligned.m8n8.x4.shared.b16 {%0,%1,%2,%3}, [%4];"
        : "=r"(r[0]), "=r"(r[1]), "=r"(r[2]), "=r"(r[3]) : "r"(addr));
}

__device__ __forceinline__ void mma16816(float* d, const uint32_t* a, uint32_t b0, uint32_t b1) {
    asm volatile("mma.sync.aligned.m16n8k16.row.col.f32.bf16.bf16.f32 "
        "{%0,%1,%2,%3}, {%4,%5,%6,%7}, {%8,%9}, {%0,%1,%2,%3};"
        : "+f"(d[0]), "+f"(d[1]), "+f"(d[2]), "+f"(d[3])
        : "r"(a[0]), "r"(a[1]), "r"(a[2]), "r"(a[3]), "r"(b0), "r"(b1));
}

// bf16 hi/lo split of one float
__device__ __forceinline__ void split1(float x, uint16_t& h, uint16_t& l) {
    uint16_t hb = __bfloat16_as_ushort(__float2bfloat16_rn(x));
    float r = __uint_as_float(((uint32_t)hb) << 16);
    uint16_t lb = __bfloat16_as_ushort(__float2bfloat16_rn(x - r));
    h = hb; l = lb;
}
// split two floats -> packed hi u32, lo u32 (lo16 = first)
__device__ __forceinline__ void split2(float a, float b, uint32_t& h, uint32_t& l) {
    uint16_t ha, la, hb2, lb2;
    split1(a, ha, la); split1(b, hb2, lb2);
    h = (uint32_t)ha | ((uint32_t)hb2 << 16);
    l = (uint32_t)la | ((uint32_t)lb2 << 16);
}

// swizzled tile byte offset: row-major, 128B rows, 16B granules XORed
__device__ __forceinline__ uint32_t sw_off(int row, int c4) {
    return (uint32_t)(row * 128 + ((c4 ^ (row & 7)) << 4));
}

// ---------------- SMEM layout (byte offsets) ----------------
#define SM_B1    0       // 64 f32
#define SM_B2    256     // 64 f32
#define SM_BO    512     // 17 f32
#define SM_WRGB  640     // 48 f32
#define SM_BRGB  832     // 3 f32
#define SM_AH    1024    // 128 rows x 128B
#define SM_AL    17408
#define SM_W1H   33792   // 64 rows x 128B
#define SM_W1L   41984
#define SM_W2H   50176
#define SM_W2L   58368
#define SM_WOH   66560   // 32 rows x 128B
#define SM_WOL   70656
#define SM_OUT   74752   // 128 x 20 f32 = 10240
#define SM_TOTAL 84992

__global__ void dt_kernel(const float* __restrict__ tmin,
                          const float* __restrict__ tmax, int n) {
    __shared__ float red[256];
    int tid = threadIdx.x;
    float acc = 0.f;
    for (int i = tid; i < n; i += 256) acc += tmax[i] - tmin[i];
    red[tid] = acc;
    __syncthreads();
    for (int s = 128; s > 0; s >>= 1) {
        if (tid < s) red[tid] += red[tid + s];
        __syncthreads();
    }
    if (tid == 0) g_dt = (red[0] / (float)n) / (float)SS;
}

// compute one layer: C[32x64 per warp] = A(128x64) * W(64xN)^T, 3-pass hi/lo
// then epilogue handled by caller via acc arrays.
__global__ void __launch_bounds__(128)
nerf_mma_kernel(const float* __restrict__ ox, const float* __restrict__ oy,
                const float* __restrict__ oz, const float* __restrict__ dxv,
                const float* __restrict__ dyv, const float* __restrict__ dzv,
                const float* __restrict__ tmin, const float* __restrict__ tmax,
                const float* __restrict__ W1, const float* __restrict__ b1,
                const float* __restrict__ W2, const float* __restrict__ b2,
                const float* __restrict__ Wo, const float* __restrict__ bo,
                const float* __restrict__ Wrgb, const float* __restrict__ brgb,
                float* __restrict__ out, int n)
{
    extern __shared__ __align__(1024) char smem[];
    const uint32_t sb = smem_to_u32(smem);
    const int tid = threadIdx.x;
    const int wid = tid >> 5, lid = tid & 31;
    const int wbase = wid * 32;

    // ---- stage weights: [n][k] bf16 hi/lo, swizzled ----
    // W1: gmem [63][64] k-major; tile rows n=0..63, k=0..63 (k=63 -> 0)
    for (int idx = tid; idx < 64 * 64; idx += 128) {
        int nn = idx >> 6, k = idx & 63;
        float w = (k < 63) ? W1[k * 64 + nn] : 0.f;
        uint16_t h, l; split1(w, h, l);
        uint32_t off = sw_off(nn, k >> 3) + (k & 7) * 2;
        *(uint16_t*)(smem + SM_W1H + off) = h;
        *(uint16_t*)(smem + SM_W1L + off) = l;
    }
    for (int idx = tid; idx < 64 * 64; idx += 128) {
        int nn = idx >> 6, k = idx & 63;
        float w = W2[k * 64 + nn];
        uint16_t h, l; split1(w, h, l);
        uint32_t off = sw_off(nn, k >> 3) + (k & 7) * 2;
        *(uint16_t*)(smem + SM_W2H + off) = h;
        *(uint16_t*)(smem + SM_W2L + off) = l;
    }
    for (int idx = tid; idx < 32 * 64; idx += 128) {
        int nn = idx >> 6, k = idx & 63;
        float w = (nn < 17) ? Wo[k * 17 + nn] : 0.f;
        uint16_t h, l; split1(w, h, l);
        uint32_t off = sw_off(nn, k >> 3) + (k & 7) * 2;
        *(uint16_t*)(smem + SM_WOH + off) = h;
        *(uint16_t*)(smem + SM_WOL + off) = l;
    }
    {
        float* s = (float*)smem;
        for (int i = tid; i < 64; i += 128) s[(SM_B1 >> 2) + i] = b1[i];
        for (int i = tid; i < 64; i += 128) s[(SM_B2 >> 2) + i] = b2[i];
        for (int i = tid; i < 17; i += 128) s[(SM_BO >> 2) + i] = bo[i];
        for (int i = tid; i < 48; i += 128) s[(SM_WRGB >> 2) + i] = Wrgb[i];
        for (int i = tid; i < 3;  i += 128) s[(SM_BRGB >> 2) + i] = brgb[i];
    }

    // ---- positional encodings -> A tile (row = sample = tid) ----
    const int ray = blockIdx.x;
    const float tmn = tmin[ray], tmx = tmax[ray];
    const float t  = fmaf((float)tid * (1.0f / (float)(SS - 1)), tmx - tmn, tmn);
    float e[64];
    e[0] = fmaf(dxv[ray], t, ox[ray]);
    e[1] = fmaf(dyv[ray], t, oy[ray]);
    e[2] = fmaf(dzv[ray], t, oz[ray]);
    e[63] = 0.f;
#pragma unroll 1
    for (int c = 0; c < 3; c++) {
        float sv, cv;
        sincosf(e[c], &sv, &cv);
#pragma unroll
        for (int f = 0; f < LFREQ; f++) {
            e[3 + 20 * c + f]      = sv;
            e[3 + 20 * c + 10 + f] = cv;
            float ns = 2.0f * sv * cv;
            float nc = fmaf(cv, cv, -(sv * sv));
            sv = ns; cv = nc;
        }
    }
    {
        uint32_t hi[32], lo[32];
#pragma unroll
        for (int j = 0; j < 32; j++) split2(e[2 * j], e[2 * j + 1], hi[j], lo[j]);
#pragma unroll
        for (int q = 0; q < 8; q++) {
            uint32_t off = sw_off(tid, q);
            *(uint4*)(smem + SM_AH + off) = make_uint4(hi[4*q], hi[4*q+1], hi[4*q+2], hi[4*q+3]);
            *(uint4*)(smem + SM_AL + off) = make_uint4(lo[4*q], lo[4*q+1], lo[4*q+2], lo[4*q+3]);
        }
    }
    __syncthreads();

    // lane-derived ldmatrix coordinates
    const int lj = lid >> 3, lr = lid & 7;
    const int a_rl  = ((lj & 1) << 3) + lr;   // row within 16-row m-tile
    const int a_c4h = lj >> 1;                // +0/+1 granule (k half)
    const int b_nl  = ((lj >> 1) << 3) + lr;  // n within 16-n pair
    const int b_c4h = lj & 1;

    // ================= layers 1 & 2 (N=64) =================
#pragma unroll 1
    for (int layer = 0; layer < 2; layer++) {
        const uint32_t WH = sb + ((layer == 0) ? SM_W1H : SM_W2H);
        const uint32_t WL = sb + ((layer == 0) ? SM_W1L : SM_W2L);
        float acc[2][8][4];
#pragma unroll
        for (int mt = 0; mt < 2; mt++)
#pragma unroll
            for (int j = 0; j < 8; j++)
#pragma unroll
                for (int v = 0; v < 4; v++) acc[mt][j][v] = 0.f;

#pragma unroll
        for (int ks = 0; ks < 4; ks++) {
            uint32_t ah[2][4], al[2][4], wh[4][4], wl[4][4];
#pragma unroll
            for (int mt = 0; mt < 2; mt++) {
                int row = wbase + mt * 16 + a_rl;
                int c4 = ks * 2 + a_c4h;
                uint32_t off = sw_off(row, c4);
                ldsm4(ah[mt], sb + SM_AH + off);
                ldsm4(al[mt], sb + SM_AL + off);
            }
#pragma unroll
            for (int p = 0; p < 4; p++) {
                int nn = p * 16 + b_nl;
                int c4 = ks * 2 + b_c4h;
                uint32_t off = sw_off(nn, c4);
                ldsm4(wh[p], WH + off);
                ldsm4(wl[p], WL + off);
            }
#pragma unroll
            for (int mt = 0; mt < 2; mt++)
#pragma unroll
                for (int p = 0; p < 4; p++) {
                    // n-tile 2p
                    mma16816(acc[mt][2*p],   ah[mt], wh[p][0], wh[p][1]);
                    mma16816(acc[mt][2*p],   ah[mt], wl[p][0], wl[p][1]);
                    mma16816(acc[mt][2*p],   al[mt], wh[p][0], wh[p][1]);
                    // n-tile 2p+1
                    mma16816(acc[mt][2*p+1], ah[mt], wh[p][2], wh[p][3]);
                    mma16816(acc[mt][2*p+1], ah[mt], wl[p][2], wl[p][3]);
                    mma16816(acc[mt][2*p+1], al[mt], wh[p][2], wh[p][3]);
                }
        }

        // epilogue: bias + relu + split -> back into A tiles
        const float* bias = (const float*)(smem + ((layer == 0) ? SM_B1 : SM_B2));
        __syncwarp();
#pragma unroll
        for (int mt = 0; mt < 2; mt++)
#pragma unroll
            for (int j = 0; j < 8; j++) {
                int cb = 8 * j + 2 * (lid & 3);
                int r0 = wbase + mt * 16 + (lid >> 2);
                float v0 = fmaxf(acc[mt][j][0] + bias[cb],     0.f);
                float v1 = fmaxf(acc[mt][j][1] + bias[cb + 1], 0.f);
                float v2 = fmaxf(acc[mt][j][2] + bias[cb],     0.f);
                float v3 = fmaxf(acc[mt][j][3] + bias[cb + 1], 0.f);
                uint32_t h01, l01, h23, l23;
                split2(v0, v1, h01, l01);
                split2(v2, v3, h23, l23);
                uint32_t o0 = sw_off(r0, j) + (cb & 7) * 2;
                uint32_t o1 = sw_off(r0 + 8, j) + (cb & 7) * 2;
                *(uint32_t*)(smem + SM_AH + o0) = h01;
                *(uint32_t*)(smem + SM_AL + o0) = l01;
                *(uint32_t*)(smem + SM_AH + o1) = h23;
                *(uint32_t*)(smem + SM_AL + o1) = l23;
            }
        __syncwarp();
    }

    // ================= layer 3 (N=32, cols 0..16 valid) =================
    {
        float acc[2][4][4];
#pragma unroll
        for (int mt = 0; mt < 2; mt++)
#pragma unroll
            for (int j = 0; j < 4; j++)
#pragma unroll
                for (int v = 0; v < 4; v++) acc[mt][j][v] = 0.f;

#pragma unroll
        for (int ks = 0; ks < 4; ks++) {
            uint32_t ah[2][4], al[2][4], wh[2][4], wl[2][4];
#pragma unroll
            for (int mt = 0; mt < 2; mt++) {
                int row = wbase + mt * 16 + a_rl;
                int c4 = ks * 2 + a_c4h;
                uint32_t off = sw_off(row, c4);
                ldsm4(ah[mt], sb + SM_AH + off);
                ldsm4(al[mt], sb + SM_AL + off);
            }
#pragma unroll
            for (int p = 0; p < 2; p++) {
                int nn = p * 16 + b_nl;
                int c4 = ks * 2 + b_c4h;
                uint32_t off = sw_off(nn, c4);
                ldsm4(wh[p], sb + SM_WOH + off);
                ldsm4(wl[p], sb + SM_WOL + off);
            }
#pragma unroll
            for (int mt = 0; mt < 2; mt++)
#pragma unroll
                for (int p = 0; p < 2; p++) {
                    mma16816(acc[mt][2*p],   ah[mt], wh[p][0], wh[p][1]);
                    mma16816(acc[mt][2*p],   ah[mt], wl[p][0], wl[p][1]);
                    mma16816(acc[mt][2*p],   al[mt], wh[p][0], wh[p][1]);
                    mma16816(acc[mt][2*p+1], ah[mt], wh[p][2], wh[p][3]);
                    mma16816(acc[mt][2*p+1], ah[mt], wl[p][2], wl[p][3]);
                    mma16816(acc[mt][2*p+1], al[mt], wh[p][2], wh[p][3]);
                }
        }

        // write cols 0..16 (+bias) to SM_OUT (f32, stride 20)
        const float* bos = (const float*)(smem + SM_BO);
        float* po = (float*)(smem + SM_OUT);
#pragma unroll
        for (int mt = 0; mt < 2; mt++)
#pragma unroll
            for (int j = 0; j < 3; j++) {
                int cb = 8 * j + 2 * (lid & 3);
                if (cb <= 16) {
                    int r0 = wbase + mt * 16 + (lid >> 2);
                    float bv0 = bos[cb];
                    float bv1 = (cb + 1 < 17) ? bos[cb + 1] : 0.f;
                    po[r0 * 20 + cb]           = acc[mt][j][0] + bv0;
                    po[r0 * 20 + cb + 1]       = acc[mt][j][1] + bv1;
                    po[(r0 + 8) * 20 + cb]     = acc[mt][j][2] + bv0;
                    po[(r0 + 8) * 20 + cb + 1] = acc[mt][j][3] + bv1;
                }
            }
    }
    __syncthreads();

    // ---------------- per-sample tail ----------------
    const float* myo = (const float*)(smem + SM_OUT) + tid * 20;
    const float sigma = fmaxf(myo[0], 0.f);
    const float* wrgb = (const float*)(smem + SM_WRGB);
    const float* brg  = (const float*)(smem + SM_BRGB);
    float rgbv[3];
#pragma unroll
    for (int cc = 0; cc < 3; cc++) {
        float r = brg[cc];
#pragma unroll
        for (int k = 0; k < 16; k++) r = fmaf(myo[1 + k], wrgb[k * 3 + cc], r);
        rgbv[cc] = 1.0f / (1.0f + expf(-r));
    }

    const float dtv   = g_dt;
    const float alpha = 1.0f - expf(-sigma * dtv);
    const float q     = (1.0f - alpha) + 1e-10f;

    float p = q;
#pragma unroll
    for (int d = 1; d < 32; d <<= 1) {
        float u = __shfl_up_sync(0xffffffffu, p, d);
        if (lid >= d) p *= u;
    }
    __shared__ float wtot[4];
    if (lid == 31) wtot[wid] = p;
    __syncthreads();
    float pre = 1.0f;
    for (int w = 0; w < wid; w++) pre *= wtot[w];
    float excl = __shfl_up_sync(0xffffffffu, p, 1);
    if (lid == 0) excl = 1.0f;
    const float T    = pre * excl;
    const float incl = pre * p;
    const float wgt  = (T > 1e-4f) ? (T * alpha) : 0.f;

    float v0 = wgt * rgbv[0], v1 = wgt * rgbv[1], v2 = wgt * rgbv[2];
#pragma unroll
    for (int off = 16; off > 0; off >>= 1) {
        v0 += __shfl_down_sync(0xffffffffu, v0, off);
        v1 += __shfl_down_sync(0xffffffffu, v1, off);
        v2 += __shfl_down_sync(0xffffffffu, v2, off);
    }
    __shared__ float redc[4][3];
    if (lid == 0) { redc[wid][0] = v0; redc[wid][1] = v1; redc[wid][2] = v2; }
    if (tid == SS - 1) out[3 * n + ray] = incl;
    __syncthreads();
    if (tid == 0) {
        out[ray * 3 + 0] = redc[0][0] + redc[1][0] + redc[2][0] + redc[3][0];
        out[ray * 3 + 1] = redc[0][1] + redc[1][1] + redc[2][1] + redc[3][1];
        out[ray * 3 + 2] = redc[0][2] + redc[1][2] + redc[2][2] + redc[3][2];
    }
}

extern "C" void kernel_launch(void* const* d_in, const int* in_sizes, int n_in,
                              void* d_out, int out_size) {
    const float* ox   = (const float*)d_in[0];
    const float* oy   = (const float*)d_in[1];
    const float* oz   = (const float*)d_in[2];
    const float* dxv  = (const float*)d_in[3];
    const float* dyv  = (const float*)d_in[4];
    const float* dzv  = (const float*)d_in[5];
    const float* tmin = (const float*)d_in[6];
    const float* tmax = (const float*)d_in[7];
    const float* W1   = (const float*)d_in[8];
    const float* b1   = (const float*)d_in[9];
    const float* W2   = (const float*)d_in[10];
    const float* b2   = (const float*)d_in[11];
    const float* Wo   = (const float*)d_in[12];
    const float* bo   = (const float*)d_in[13];
    const float* Wrgb = (const float*)d_in[14];
    const float* brgb = (const float*)d_in[15];
    float* out = (float*)d_out;
    const int n = in_sizes[0];

    cudaFuncSetAttribute(nerf_mma_kernel, cudaFuncAttributeMaxDynamicSharedMemorySize, SM_TOTAL);

    dt_kernel<<<1, 256>>>(tmin, tmax, n);
    nerf_mma_kernel<<<n, 128, SM_TOTAL>>>(ox, oy, oz, dxv, dyv, dzv, tmin, tmax,
                                          W1, b1, W2, b2, Wo, bo, Wrgb, brgb, out, n);
}

// round 5
// speedup vs baseline: 4.6176x; 2.4808x over previous
#include <cuda_runtime.h>
#include <cuda_bf16.h>
#include <cstdint>
#include <math.h>

#define SS    128
#define LFREQ 10

__device__ float g_dt;
__device__ __align__(16) unsigned char g_wbuf[40960];   // pre-swizzled bf16 hi/lo weights

// g_wbuf layout (bytes)
#define GW_W1H 0
#define GW_W1L 8192
#define GW_W2H 16384
#define GW_W2L 24576
#define GW_WOH 32768
#define GW_WOL 36864

// ---------------- helpers ----------------
__device__ __forceinline__ uint32_t smem_to_u32(const void* p) {
    uint32_t a;
    asm("{ .reg .u64 t; cvta.to.shared.u64 t, %1; cvt.u32.u64 %0, t; }" : "=r"(a) : "l"(p));
    return a;
}

__device__ __forceinline__ void ldsm4(uint32_t* r, uint32_t addr) {
    asm volatile("ldmatrix.sync.aligned.m8n8.x4.shared.b16 {%0,%1,%2,%3}, [%4];"
        : "=r"(r[0]), "=r"(r[1]), "=r"(r[2]), "=r"(r[3]) : "r"(addr));
}

__device__ __forceinline__ void mma16816(float* d, const uint32_t* a, uint32_t b0, uint32_t b1) {
    asm volatile("mma.sync.aligned.m16n8k16.row.col.f32.bf16.bf16.f32 "
        "{%0,%1,%2,%3}, {%4,%5,%6,%7}, {%8,%9}, {%0,%1,%2,%3};"
        : "+f"(d[0]), "+f"(d[1]), "+f"(d[2]), "+f"(d[3])
        : "r"(a[0]), "r"(a[1]), "r"(a[2]), "r"(a[3]), "r"(b0), "r"(b1));
}

__device__ __forceinline__ void split1(float x, uint16_t& h, uint16_t& l) {
    uint16_t hb = __bfloat16_as_ushort(__float2bfloat16_rn(x));
    float r = __uint_as_float(((uint32_t)hb) << 16);
    uint16_t lb = __bfloat16_as_ushort(__float2bfloat16_rn(x - r));
    h = hb; l = lb;
}
__device__ __forceinline__ void split2(float a, float b, uint32_t& h, uint32_t& l) {
    uint16_t ha, la, hb2, lb2;
    split1(a, ha, la); split1(b, hb2, lb2);
    h = (uint32_t)ha | ((uint32_t)hb2 << 16);
    l = (uint32_t)la | ((uint32_t)lb2 << 16);
}

// swizzled tile byte offset: row-major, 128B rows, 16B granules XORed
__device__ __forceinline__ uint32_t sw_off(int row, int c4) {
    return (uint32_t)(row * 128 + ((c4 ^ (row & 7)) << 4));
}

// ---------------- SMEM layout (byte offsets) ----------------
#define SM_B1    0       // 64 f32
#define SM_B2    256     // 64 f32
#define SM_BO    512     // 17 f32
#define SM_WRGB  640     // 48 f32
#define SM_BRGB  832     // 3 f32
#define SM_W     1024    // 40960B of weight tiles (same order as g_wbuf)
#define SM_W1H   (SM_W + GW_W1H)
#define SM_W1L   (SM_W + GW_W1L)
#define SM_W2H   (SM_W + GW_W2H)
#define SM_W2L   (SM_W + GW_W2L)
#define SM_WOH   (SM_W + GW_WOH)
#define SM_WOL   (SM_W + GW_WOL)
#define SM_A     41984   // 2 rays x (16384 hi + 16384 lo)
#define SM_TOTAL (41984 + 65536)   // 107520

#define TPB 256
#define RAYS_PER_CTA 2

// -------- prep: dt reduction + weight conversion (one CTA) --------
__global__ void prep_kernel(const float* __restrict__ tmin, const float* __restrict__ tmax,
                            const float* __restrict__ W1, const float* __restrict__ W2,
                            const float* __restrict__ Wo, int n) {
    __shared__ float red[256];
    int tid = threadIdx.x;
    float acc = 0.f;
    for (int i = tid; i < n; i += 256) acc += tmax[i] - tmin[i];
    red[tid] = acc;
    __syncthreads();
    for (int s = 128; s > 0; s >>= 1) {
        if (tid < s) red[tid] += red[tid + s];
        __syncthreads();
    }
    if (tid == 0) g_dt = (red[0] / (float)n) / (float)SS;

    // W1: [63][64] -> tile [n=64][k=64], k=63 zero-padded
    for (int idx = tid; idx < 64 * 64; idx += 256) {
        int nn = idx >> 6, k = idx & 63;
        float w = (k < 63) ? W1[k * 64 + nn] : 0.f;
        uint16_t h, l; split1(w, h, l);
        uint32_t off = sw_off(nn, k >> 3) + (k & 7) * 2;
        *(uint16_t*)(g_wbuf + GW_W1H + off) = h;
        *(uint16_t*)(g_wbuf + GW_W1L + off) = l;
    }
    for (int idx = tid; idx < 64 * 64; idx += 256) {
        int nn = idx >> 6, k = idx & 63;
        float w = W2[k * 64 + nn];
        uint16_t h, l; split1(w, h, l);
        uint32_t off = sw_off(nn, k >> 3) + (k & 7) * 2;
        *(uint16_t*)(g_wbuf + GW_W2H + off) = h;
        *(uint16_t*)(g_wbuf + GW_W2L + off) = l;
    }
    for (int idx = tid; idx < 32 * 64; idx += 256) {
        int nn = idx >> 6, k = idx & 63;
        float w = (nn < 17) ? Wo[k * 17 + nn] : 0.f;
        uint16_t h, l; split1(w, h, l);
        uint32_t off = sw_off(nn, k >> 3) + (k & 7) * 2;
        *(uint16_t*)(g_wbuf + GW_WOH + off) = h;
        *(uint16_t*)(g_wbuf + GW_WOL + off) = l;
    }
}

__global__ void __launch_bounds__(TPB, 2)
nerf_mma_kernel(const float* __restrict__ ox, const float* __restrict__ oy,
                const float* __restrict__ oz, const float* __restrict__ dxv,
                const float* __restrict__ dyv, const float* __restrict__ dzv,
                const float* __restrict__ tmin, const float* __restrict__ tmax,
                const float* __restrict__ b1, const float* __restrict__ b2,
                const float* __restrict__ bo,
                const float* __restrict__ Wrgb, const float* __restrict__ brgb,
                float* __restrict__ out, int n)
{
    extern __shared__ __align__(1024) char smem[];
    const uint32_t sb = smem_to_u32(smem);
    const int tid  = threadIdx.x;
    const int rayi = tid >> 7;          // ray within CTA
    const int rtid = tid & 127;         // sample within ray
    const int wid  = tid >> 5;
    const int lid  = tid & 31;
    const int wray = wid & 3;           // warp within ray
    const int wbase = wray * 32;
    const uint32_t AH = SM_A + rayi * 32768;
    const uint32_t AL = AH + 16384;

    // ---- stage weights: straight vector copy of preconverted tiles ----
    {
        const uint4* src = (const uint4*)g_wbuf;
        uint4* dst = (uint4*)(smem + SM_W);
        for (int i = tid; i < 2560; i += TPB) dst[i] = src[i];
        float* s = (float*)smem;
        for (int i = tid; i < 64; i += TPB) s[(SM_B1 >> 2) + i] = b1[i];
        for (int i = tid; i < 64; i += TPB) s[(SM_B2 >> 2) + i] = b2[i];
        for (int i = tid; i < 17; i += TPB) s[(SM_BO >> 2) + i] = bo[i];
        for (int i = tid; i < 48; i += TPB) s[(SM_WRGB >> 2) + i] = Wrgb[i];
        for (int i = tid; i < 3;  i += TPB) s[(SM_BRGB >> 2) + i] = brgb[i];
    }

    // ---- positional encodings -> A tile (row = sample = rtid) ----
    const int ray = blockIdx.x * RAYS_PER_CTA + rayi;
    const float tmn = tmin[ray], tmx = tmax[ray];
    const float t  = fmaf((float)rtid * (1.0f / (float)(SS - 1)), tmx - tmn, tmn);
    float e[64];
    e[0] = fmaf(dxv[ray], t, ox[ray]);
    e[1] = fmaf(dyv[ray], t, oy[ray]);
    e[2] = fmaf(dzv[ray], t, oz[ray]);
    e[63] = 0.f;
#pragma unroll 1
    for (int c = 0; c < 3; c++) {
        float sv, cv;
        sincosf(e[c], &sv, &cv);
#pragma unroll
        for (int f = 0; f < LFREQ; f++) {
            e[3 + 20 * c + f]      = sv;
            e[3 + 20 * c + 10 + f] = cv;
            float ns = 2.0f * sv * cv;
            float nc = fmaf(cv, cv, -(sv * sv));
            sv = ns; cv = nc;
        }
    }
    {
        uint32_t hi[32], lo[32];
#pragma unroll
        for (int j = 0; j < 32; j++) split2(e[2 * j], e[2 * j + 1], hi[j], lo[j]);
#pragma unroll
        for (int q = 0; q < 8; q++) {
            uint32_t off = sw_off(rtid, q);
            *(uint4*)(smem + AH + off) = make_uint4(hi[4*q], hi[4*q+1], hi[4*q+2], hi[4*q+3]);
            *(uint4*)(smem + AL + off) = make_uint4(lo[4*q], lo[4*q+1], lo[4*q+2], lo[4*q+3]);
        }
    }
    __syncthreads();

    // lane-derived ldmatrix coordinates
    const int lj = lid >> 3, lr = lid & 7;
    const int a_rl  = ((lj & 1) << 3) + lr;
    const int a_c4h = lj >> 1;
    const int b_nl  = ((lj >> 1) << 3) + lr;
    const int b_c4h = lj & 1;

    // ================= layers 1 & 2 (N=64) =================
#pragma unroll 1
    for (int layer = 0; layer < 2; layer++) {
        const uint32_t WH = sb + ((layer == 0) ? SM_W1H : SM_W2H);
        const uint32_t WL = sb + ((layer == 0) ? SM_W1L : SM_W2L);
        float acc[2][8][4];
#pragma unroll
        for (int mt = 0; mt < 2; mt++)
#pragma unroll
            for (int j = 0; j < 8; j++)
#pragma unroll
                for (int v = 0; v < 4; v++) acc[mt][j][v] = 0.f;

#pragma unroll
        for (int ks = 0; ks < 4; ks++) {
            uint32_t ah[2][4], al[2][4], wh[4][4], wl[4][4];
#pragma unroll
            for (int mt = 0; mt < 2; mt++) {
                int row = wbase + mt * 16 + a_rl;
                int c4 = ks * 2 + a_c4h;
                uint32_t off = sw_off(row, c4);
                ldsm4(ah[mt], sb + AH + off);
                ldsm4(al[mt], sb + AL + off);
            }
#pragma unroll
            for (int p = 0; p < 4; p++) {
                int nn = p * 16 + b_nl;
                int c4 = ks * 2 + b_c4h;
                uint32_t off = sw_off(nn, c4);
                ldsm4(wh[p], WH + off);
                ldsm4(wl[p], WL + off);
            }
#pragma unroll
            for (int mt = 0; mt < 2; mt++)
#pragma unroll
                for (int p = 0; p < 4; p++) {
                    mma16816(acc[mt][2*p],   ah[mt], wh[p][0], wh[p][1]);
                    mma16816(acc[mt][2*p],   ah[mt], wl[p][0], wl[p][1]);
                    mma16816(acc[mt][2*p],   al[mt], wh[p][0], wh[p][1]);
                    mma16816(acc[mt][2*p+1], ah[mt], wh[p][2], wh[p][3]);
                    mma16816(acc[mt][2*p+1], ah[mt], wl[p][2], wl[p][3]);
                    mma16816(acc[mt][2*p+1], al[mt], wh[p][2], wh[p][3]);
                }
        }

        // epilogue: bias + relu + split -> back into A tiles (warp-private rows)
        const float* bias = (const float*)(smem + ((layer == 0) ? SM_B1 : SM_B2));
        __syncwarp();
#pragma unroll
        for (int mt = 0; mt < 2; mt++)
#pragma unroll
            for (int j = 0; j < 8; j++) {
                int cb = 8 * j + 2 * (lid & 3);
                int r0 = wbase + mt * 16 + (lid >> 2);
                float v0 = fmaxf(acc[mt][j][0] + bias[cb],     0.f);
                float v1 = fmaxf(acc[mt][j][1] + bias[cb + 1], 0.f);
                float v2 = fmaxf(acc[mt][j][2] + bias[cb],     0.f);
                float v3 = fmaxf(acc[mt][j][3] + bias[cb + 1], 0.f);
                uint32_t h01, l01, h23, l23;
                split2(v0, v1, h01, l01);
                split2(v2, v3, h23, l23);
                uint32_t o0 = sw_off(r0, j) + (cb & 7) * 2;
                uint32_t o1 = sw_off(r0 + 8, j) + (cb & 7) * 2;
                *(uint32_t*)(smem + AH + o0) = h01;
                *(uint32_t*)(smem + AL + o0) = l01;
                *(uint32_t*)(smem + AH + o1) = h23;
                *(uint32_t*)(smem + AL + o1) = l23;
            }
        __syncwarp();
    }

    // ================= layer 3 (N=32, cols 0..16 valid) =================
    float acc3[2][4][4];
    {
#pragma unroll
        for (int mt = 0; mt < 2; mt++)
#pragma unroll
            for (int j = 0; j < 4; j++)
#pragma unroll
                for (int v = 0; v < 4; v++) acc3[mt][j][v] = 0.f;

#pragma unroll
        for (int ks = 0; ks < 4; ks++) {
            uint32_t ah[2][4], al[2][4], wh[2][4], wl[2][4];
#pragma unroll
            for (int mt = 0; mt < 2; mt++) {
                int row = wbase + mt * 16 + a_rl;
                int c4 = ks * 2 + a_c4h;
                uint32_t off = sw_off(row, c4);
                ldsm4(ah[mt], sb + AH + off);
                ldsm4(al[mt], sb + AL + off);
            }
#pragma unroll
            for (int p = 0; p < 2; p++) {
                int nn = p * 16 + b_nl;
                int c4 = ks * 2 + b_c4h;
                uint32_t off = sw_off(nn, c4);
                ldsm4(wh[p], sb + SM_WOH + off);
                ldsm4(wl[p], sb + SM_WOL + off);
            }
#pragma unroll
            for (int mt = 0; mt < 2; mt++)
#pragma unroll
                for (int p = 0; p < 2; p++) {
                    mma16816(acc3[mt][2*p],   ah[mt], wh[p][0], wh[p][1]);
                    mma16816(acc3[mt][2*p],   ah[mt], wl[p][0], wl[p][1]);
                    mma16816(acc3[mt][2*p],   al[mt], wh[p][0], wh[p][1]);
                    mma16816(acc3[mt][2*p+1], ah[mt], wh[p][2], wh[p][3]);
                    mma16816(acc3[mt][2*p+1], ah[mt], wl[p][2], wl[p][3]);
                    mma16816(acc3[mt][2*p+1], al[mt], wh[p][2], wh[p][3]);
                }
        }
    }

    // A tiles dead for this ray after all warps pass this barrier; alias OUT onto AH
    __syncthreads();
    {
        const float* bos = (const float*)(smem + SM_BO);
        float* po = (float*)(smem + AH);   // 128 rows x 20 f32 = 10240B (< 16384)
#pragma unroll
        for (int mt = 0; mt < 2; mt++)
#pragma unroll
            for (int j = 0; j < 3; j++) {
                int cb = 8 * j + 2 * (lid & 3);
                if (cb <= 16) {
                    int r0 = wbase + mt * 16 + (lid >> 2);
                    float bv0 = bos[cb];
                    float bv1 = (cb + 1 < 17) ? bos[cb + 1] : 0.f;
                    po[r0 * 20 + cb]           = acc3[mt][j][0] + bv0;
                    po[r0 * 20 + cb + 1]       = acc3[mt][j][1] + bv1;
                    po[(r0 + 8) * 20 + cb]     = acc3[mt][j][2] + bv0;
                    po[(r0 + 8) * 20 + cb + 1] = acc3[mt][j][3] + bv1;
                }
            }
    }
    __syncthreads();

    // ---------------- per-sample tail ----------------
    const float* myo = (const float*)(smem + AH) + rtid * 20;
    const float sigma = fmaxf(myo[0], 0.f);
    const float* wrgb = (const float*)(smem + SM_WRGB);
    const float* brg  = (const float*)(smem + SM_BRGB);
    float rgbv[3];
#pragma unroll
    for (int cc = 0; cc < 3; cc++) {
        float r = brg[cc];
#pragma unroll
        for (int k = 0; k < 16; k++) r = fmaf(myo[1 + k], wrgb[k * 3 + cc], r);
        rgbv[cc] = 1.0f / (1.0f + expf(-r));
    }

    const float dtv   = g_dt;
    const float alpha = 1.0f - expf(-sigma * dtv);
    const float q     = (1.0f - alpha) + 1e-10f;

    float p = q;
#pragma unroll
    for (int d = 1; d < 32; d <<= 1) {
        float u = __shfl_up_sync(0xffffffffu, p, d);
        if (lid >= d) p *= u;
    }
    __shared__ float wtot[RAYS_PER_CTA][4];
    if (lid == 31) wtot[rayi][wray] = p;
    __syncthreads();
    float pre = 1.0f;
    for (int w = 0; w < wray; w++) pre *= wtot[rayi][w];
    float excl = __shfl_up_sync(0xffffffffu, p, 1);
    if (lid == 0) excl = 1.0f;
    const float T    = pre * excl;
    const float incl = pre * p;
    const float wgt  = (T > 1e-4f) ? (T * alpha) : 0.f;

    float v0 = wgt * rgbv[0], v1 = wgt * rgbv[1], v2 = wgt * rgbv[2];
#pragma unroll
    for (int off = 16; off > 0; off >>= 1) {
        v0 += __shfl_down_sync(0xffffffffu, v0, off);
        v1 += __shfl_down_sync(0xffffffffu, v1, off);
        v2 += __shfl_down_sync(0xffffffffu, v2, off);
    }
    __shared__ float redc[RAYS_PER_CTA][4][3];
    if (lid == 0) { redc[rayi][wray][0] = v0; redc[rayi][wray][1] = v1; redc[rayi][wray][2] = v2; }
    if (rtid == SS - 1) out[3 * n + ray] = incl;
    __syncthreads();
    if (rtid == 0) {
        out[ray * 3 + 0] = redc[rayi][0][0] + redc[rayi][1][0] + redc[rayi][2][0] + redc[rayi][3][0];
        out[ray * 3 + 1] = redc[rayi][0][1] + redc[rayi][1][1] + redc[rayi][2][1] + redc[rayi][3][1];
        out[ray * 3 + 2] = redc[rayi][0][2] + redc[rayi][1][2] + redc[rayi][2][2] + redc[rayi][3][2];
    }
}

extern "C" void kernel_launch(void* const* d_in, const int* in_sizes, int n_in,
                              void* d_out, int out_size) {
    const float* ox   = (const float*)d_in[0];
    const float* oy   = (const float*)d_in[1];
    const float* oz   = (const float*)d_in[2];
    const float* dxv  = (const float*)d_in[3];
    const float* dyv  = (const float*)d_in[4];
    const float* dzv  = (const float*)d_in[5];
    const float* tmin = (const float*)d_in[6];
    const float* tmax = (const float*)d_in[7];
    const float* W1   = (const float*)d_in[8];
    const float* b1   = (const float*)d_in[9];
    const float* W2   = (const float*)d_in[10];
    const float* b2   = (const float*)d_in[11];
    const float* Wo   = (const float*)d_in[12];
    const float* bo   = (const float*)d_in[13];
    const float* Wrgb = (const float*)d_in[14];
    const float* brgb = (const float*)d_in[15];
    float* out = (float*)d_out;
    const int n = in_sizes[0];

    cudaFuncSetAttribute(nerf_mma_kernel, cudaFuncAttributeMaxDynamicSharedMemorySize, SM_TOTAL);

    prep_kernel<<<1, 256>>>(tmin, tmax, W1, W2, Wo, n);
    nerf_mma_kernel<<<n / RAYS_PER_CTA, TPB, SM_TOTAL>>>(
        ox, oy, oz, dxv, dyv, dzv, tmin, tmax,
        b1, b2, bo, Wrgb, brgb, out, n);
}

// round 6
// speedup vs baseline: 5.0606x; 1.0959x over previous
#include <cuda_runtime.h>
#include <cuda_bf16.h>
#include <cstdint>
#include <math.h>

#define SS    128
#define LFREQ 10

__device__ float g_dt;
__device__ __align__(16) unsigned char g_wbuf[40960];   // pre-swizzled bf16 hi/lo weights

#define GW_W1H 0
#define GW_W1L 8192
#define GW_W2H 16384
#define GW_W2L 24576
#define GW_WOH 32768
#define GW_WOL 36864

// ---------------- helpers ----------------
__device__ __forceinline__ uint32_t smem_to_u32(const void* p) {
    uint32_t a;
    asm("{ .reg .u64 t; cvta.to.shared.u64 t, %1; cvt.u32.u64 %0, t; }" : "=r"(a) : "l"(p));
    return a;
}

__device__ __forceinline__ void ldsm4(uint32_t* r, uint32_t addr) {
    asm volatile("ldmatrix.sync.aligned.m8n8.x4.shared.b16 {%0,%1,%2,%3}, [%4];"
        : "=r"(r[0]), "=r"(r[1]), "=r"(r[2]), "=r"(r[3]) : "r"(addr));
}

__device__ __forceinline__ void mma16816(float* d, const uint32_t* a, uint32_t b0, uint32_t b1) {
    asm volatile("mma.sync.aligned.m16n8k16.row.col.f32.bf16.bf16.f32 "
        "{%0,%1,%2,%3}, {%4,%5,%6,%7}, {%8,%9}, {%0,%1,%2,%3};"
        : "+f"(d[0]), "+f"(d[1]), "+f"(d[2]), "+f"(d[3])
        : "r"(a[0]), "r"(a[1]), "r"(a[2]), "r"(a[3]), "r"(b0), "r"(b1));
}

__device__ __forceinline__ void split1(float x, uint16_t& h, uint16_t& l) {
    uint16_t hb = __bfloat16_as_ushort(__float2bfloat16_rn(x));
    float r = __uint_as_float(((uint32_t)hb) << 16);
    uint16_t lb = __bfloat16_as_ushort(__float2bfloat16_rn(x - r));
    h = hb; l = lb;
}
__device__ __forceinline__ void split2(float a, float b, uint32_t& h, uint32_t& l) {
    uint16_t ha, la, hb2, lb2;
    split1(a, ha, la); split1(b, hb2, lb2);
    h = (uint32_t)ha | ((uint32_t)hb2 << 16);
    l = (uint32_t)la | ((uint32_t)lb2 << 16);
}

// swizzled tile byte offset: row-major, 128B rows, 16B granules XORed
__device__ __forceinline__ uint32_t sw_off(int row, int c4) {
    return (uint32_t)(row * 128 + ((c4 ^ (row & 7)) << 4));
}

// ---------------- SMEM layout (byte offsets) ----------------
#define SM_B1    0
#define SM_B2    256
#define SM_BO    512
#define SM_WRGB  640
#define SM_BRGB  832
#define SM_W     1024
#define SM_W1H   (SM_W + GW_W1H)
#define SM_W1L   (SM_W + GW_W1L)
#define SM_W2H   (SM_W + GW_W2H)
#define SM_W2L   (SM_W + GW_W2L)
#define SM_WOH   (SM_W + GW_WOH)
#define SM_WOL   (SM_W + GW_WOL)
#define SM_A     41984   // 2 rays x (16384 hi + 16384 lo)
#define SM_TOTAL (41984 + 65536)

#define TPB 256
#define RAYS_PER_CTA 2

// -------- prep: dt reduction + weight conversion (one CTA) --------
__global__ void prep_kernel(const float* __restrict__ tmin, const float* __restrict__ tmax,
                            const float* __restrict__ W1, const float* __restrict__ W2,
                            const float* __restrict__ Wo, int n) {
    __shared__ float red[256];
    int tid = threadIdx.x;
    float acc = 0.f;
    for (int i = tid; i < n; i += 256) acc += tmax[i] - tmin[i];
    red[tid] = acc;
    __syncthreads();
    for (int s = 128; s > 0; s >>= 1) {
        if (tid < s) red[tid] += red[tid + s];
        __syncthreads();
    }
    if (tid == 0) g_dt = (red[0] / (float)n) / (float)SS;

    for (int idx = tid; idx < 64 * 64; idx += 256) {
        int nn = idx >> 6, k = idx & 63;
        float w = (k < 63) ? W1[k * 64 + nn] : 0.f;
        uint16_t h, l; split1(w, h, l);
        uint32_t off = sw_off(nn, k >> 3) + (k & 7) * 2;
        *(uint16_t*)(g_wbuf + GW_W1H + off) = h;
        *(uint16_t*)(g_wbuf + GW_W1L + off) = l;
    }
    for (int idx = tid; idx < 64 * 64; idx += 256) {
        int nn = idx >> 6, k = idx & 63;
        float w = W2[k * 64 + nn];
        uint16_t h, l; split1(w, h, l);
        uint32_t off = sw_off(nn, k >> 3) + (k & 7) * 2;
        *(uint16_t*)(g_wbuf + GW_W2H + off) = h;
        *(uint16_t*)(g_wbuf + GW_W2L + off) = l;
    }
    for (int idx = tid; idx < 32 * 64; idx += 256) {
        int nn = idx >> 6, k = idx & 63;
        float w = (nn < 17) ? Wo[k * 17 + nn] : 0.f;
        uint16_t h, l; split1(w, h, l);
        uint32_t off = sw_off(nn, k >> 3) + (k & 7) * 2;
        *(uint16_t*)(g_wbuf + GW_WOH + off) = h;
        *(uint16_t*)(g_wbuf + GW_WOL + off) = l;
    }
}

__global__ void __launch_bounds__(TPB, 2)
nerf_mma_kernel(const float* __restrict__ ox, const float* __restrict__ oy,
                const float* __restrict__ oz, const float* __restrict__ dxv,
                const float* __restrict__ dyv, const float* __restrict__ dzv,
                const float* __restrict__ tmin, const float* __restrict__ tmax,
                const float* __restrict__ b1, const float* __restrict__ b2,
                const float* __restrict__ bo,
                const float* __restrict__ Wrgb, const float* __restrict__ brgb,
                float* __restrict__ out, int n)
{
    extern __shared__ __align__(1024) char smem[];
    const uint32_t sb = smem_to_u32(smem);
    const int tid  = threadIdx.x;
    const int rayi = tid >> 7;
    const int rtid = tid & 127;
    const int wid  = tid >> 5;
    const int lid  = tid & 31;
    const int wray = wid & 3;
    const int wbase = wray * 32;
    const uint32_t AH = SM_A + rayi * 32768;
    const uint32_t AL = AH + 16384;

    // ---- stage weights (vector copy of preconverted tiles) ----
    {
        const uint4* src = (const uint4*)g_wbuf;
        uint4* dst = (uint4*)(smem + SM_W);
        for (int i = tid; i < 2560; i += TPB) dst[i] = src[i];
        float* s = (float*)smem;
        for (int i = tid; i < 64; i += TPB) s[(SM_B1 >> 2) + i] = b1[i];
        for (int i = tid; i < 64; i += TPB) s[(SM_B2 >> 2) + i] = b2[i];
        for (int i = tid; i < 17; i += TPB) s[(SM_BO >> 2) + i] = bo[i];
        for (int i = tid; i < 48; i += TPB) s[(SM_WRGB >> 2) + i] = Wrgb[i];
        for (int i = tid; i < 3;  i += TPB) s[(SM_BRGB >> 2) + i] = brgb[i];
    }

    // ---- positional encodings -> A tile (row = sample = rtid) ----
    const int ray = blockIdx.x * RAYS_PER_CTA + rayi;
    const float tmn = tmin[ray], tmx = tmax[ray];
    const float t  = fmaf((float)rtid * (1.0f / (float)(SS - 1)), tmx - tmn, tmn);
    float e[64];
    e[0] = fmaf(dxv[ray], t, ox[ray]);
    e[1] = fmaf(dyv[ray], t, oy[ray]);
    e[2] = fmaf(dzv[ray], t, oz[ray]);
    e[63] = 0.f;
#pragma unroll 1
    for (int c = 0; c < 3; c++) {
        float sv, cv;
        sincosf(e[c], &sv, &cv);
#pragma unroll
        for (int f = 0; f < LFREQ; f++) {
            e[3 + 20 * c + f]      = sv;
            e[3 + 20 * c + 10 + f] = cv;
            float ns = 2.0f * sv * cv;
            float nc = fmaf(cv, cv, -(sv * sv));
            sv = ns; cv = nc;
        }
    }
    {
        uint32_t hi[32], lo[32];
#pragma unroll
        for (int j = 0; j < 32; j++) split2(e[2 * j], e[2 * j + 1], hi[j], lo[j]);
#pragma unroll
        for (int q = 0; q < 8; q++) {
            uint32_t off = sw_off(rtid, q);
            *(uint4*)(smem + AH + off) = make_uint4(hi[4*q], hi[4*q+1], hi[4*q+2], hi[4*q+3]);
            *(uint4*)(smem + AL + off) = make_uint4(lo[4*q], lo[4*q+1], lo[4*q+2], lo[4*q+3]);
        }
    }
    __syncthreads();

    // lane-derived ldmatrix coordinates
    const int lj = lid >> 3, lr = lid & 7;
    const int a_rl  = ((lj & 1) << 3) + lr;
    const int a_c4h = lj >> 1;
    const int b_nl  = ((lj >> 1) << 3) + lr;
    const int b_c4h = lj & 1;
    const int c2l   = 2 * (lid & 3);

    float acc[2][8][4];
    uint32_t ahr[2][4][4], alr[2][4][4];   // register A fragments (hi/lo)

    // ================= layer 1 (A from smem) =================
#pragma unroll
    for (int mt = 0; mt < 2; mt++)
#pragma unroll
        for (int j = 0; j < 8; j++)
#pragma unroll
            for (int v = 0; v < 4; v++) acc[mt][j][v] = 0.f;

#pragma unroll
    for (int ks = 0; ks < 4; ks++) {
        uint32_t ahs[2][4], als[2][4];
#pragma unroll
        for (int mt = 0; mt < 2; mt++) {
            uint32_t off = sw_off(wbase + mt * 16 + a_rl, ks * 2 + a_c4h);
            ldsm4(ahs[mt], sb + AH + off);
            ldsm4(als[mt], sb + AL + off);
        }
#pragma unroll
        for (int p = 0; p < 4; p++) {
            uint32_t wh[4], wl[4];
            uint32_t off = sw_off(p * 16 + b_nl, ks * 2 + b_c4h);
            ldsm4(wh, sb + SM_W1H + off);
            ldsm4(wl, sb + SM_W1L + off);
#pragma unroll
            for (int mt = 0; mt < 2; mt++) {
                mma16816(acc[mt][2*p],   ahs[mt], wh[0], wh[1]);
                mma16816(acc[mt][2*p],   ahs[mt], wl[0], wl[1]);
                mma16816(acc[mt][2*p],   als[mt], wh[0], wh[1]);
                mma16816(acc[mt][2*p+1], ahs[mt], wh[2], wh[3]);
                mma16816(acc[mt][2*p+1], ahs[mt], wl[2], wl[3]);
                mma16816(acc[mt][2*p+1], als[mt], wh[2], wh[3]);
            }
        }
    }

    // epilogue 1: bias+relu+split -> register A fragments
    {
        const float* bias = (const float*)(smem + SM_B1);
#pragma unroll
        for (int mt = 0; mt < 2; mt++)
#pragma unroll
            for (int j = 0; j < 8; j++) {
                int cb = 8 * j + c2l;
                float v0 = fmaxf(acc[mt][j][0] + bias[cb],     0.f);
                float v1 = fmaxf(acc[mt][j][1] + bias[cb + 1], 0.f);
                float v2 = fmaxf(acc[mt][j][2] + bias[cb],     0.f);
                float v3 = fmaxf(acc[mt][j][3] + bias[cb + 1], 0.f);
                uint32_t h01, l01, h23, l23;
                split2(v0, v1, h01, l01);
                split2(v2, v3, h23, l23);
                int s = j >> 1, hf = j & 1;
                ahr[mt][s][2*hf]   = h01; ahr[mt][s][2*hf+1] = h23;
                alr[mt][s][2*hf]   = l01; alr[mt][s][2*hf+1] = l23;
            }
    }

    // ================= layer 2 (A from registers) =================
#pragma unroll
    for (int mt = 0; mt < 2; mt++)
#pragma unroll
        for (int j = 0; j < 8; j++)
#pragma unroll
            for (int v = 0; v < 4; v++) acc[mt][j][v] = 0.f;

#pragma unroll
    for (int ks = 0; ks < 4; ks++) {
#pragma unroll
        for (int p = 0; p < 4; p++) {
            uint32_t wh[4], wl[4];
            uint32_t off = sw_off(p * 16 + b_nl, ks * 2 + b_c4h);
            ldsm4(wh, sb + SM_W2H + off);
            ldsm4(wl, sb + SM_W2L + off);
#pragma unroll
            for (int mt = 0; mt < 2; mt++) {
                mma16816(acc[mt][2*p],   ahr[mt][ks], wh[0], wh[1]);
                mma16816(acc[mt][2*p],   ahr[mt][ks], wl[0], wl[1]);
                mma16816(acc[mt][2*p],   alr[mt][ks], wh[0], wh[1]);
                mma16816(acc[mt][2*p+1], ahr[mt][ks], wh[2], wh[3]);
                mma16816(acc[mt][2*p+1], ahr[mt][ks], wl[2], wl[3]);
                mma16816(acc[mt][2*p+1], alr[mt][ks], wh[2], wh[3]);
            }
        }
    }

    // epilogue 2 -> overwrite register A fragments
    {
        const float* bias = (const float*)(smem + SM_B2);
#pragma unroll
        for (int mt = 0; mt < 2; mt++)
#pragma unroll
            for (int j = 0; j < 8; j++) {
                int cb = 8 * j + c2l;
                float v0 = fmaxf(acc[mt][j][0] + bias[cb],     0.f);
                float v1 = fmaxf(acc[mt][j][1] + bias[cb + 1], 0.f);
                float v2 = fmaxf(acc[mt][j][2] + bias[cb],     0.f);
                float v3 = fmaxf(acc[mt][j][3] + bias[cb + 1], 0.f);
                uint32_t h01, l01, h23, l23;
                split2(v0, v1, h01, l01);
                split2(v2, v3, h23, l23);
                int s = j >> 1, hf = j & 1;
                ahr[mt][s][2*hf]   = h01; ahr[mt][s][2*hf+1] = h23;
                alr[mt][s][2*hf]   = l01; alr[mt][s][2*hf+1] = l23;
            }
    }

    // ================= layer 3 (N=32, cols 0..16 valid) =================
#pragma unroll
    for (int mt = 0; mt < 2; mt++)
#pragma unroll
        for (int j = 0; j < 4; j++)
#pragma unroll
            for (int v = 0; v < 4; v++) acc[mt][j][v] = 0.f;

#pragma unroll
    for (int ks = 0; ks < 4; ks++) {
#pragma unroll
        for (int p = 0; p < 2; p++) {
            uint32_t wh[4], wl[4];
            uint32_t off = sw_off(p * 16 + b_nl, ks * 2 + b_c4h);
            ldsm4(wh, sb + SM_WOH + off);
            ldsm4(wl, sb + SM_WOL + off);
#pragma unroll
            for (int mt = 0; mt < 2; mt++) {
                mma16816(acc[mt][2*p],   ahr[mt][ks], wh[0], wh[1]);
                mma16816(acc[mt][2*p],   ahr[mt][ks], wl[0], wl[1]);
                mma16816(acc[mt][2*p],   alr[mt][ks], wh[0], wh[1]);
                mma16816(acc[mt][2*p+1], ahr[mt][ks], wh[2], wh[3]);
                mma16816(acc[mt][2*p+1], ahr[mt][ks], wl[2], wl[3]);
                mma16816(acc[mt][2*p+1], alr[mt][ks], wh[2], wh[3]);
            }
        }
    }

    // A tiles dead (layers 2-3 ran from registers); alias OUT staging onto AH
    __syncthreads();
    {
        const float* bos = (const float*)(smem + SM_BO);
        float* po = (float*)(smem + AH);   // 128 rows x 20 f32
#pragma unroll
        for (int mt = 0; mt < 2; mt++)
#pragma unroll
            for (int j = 0; j < 3; j++) {
                int cb = 8 * j + c2l;
                if (cb <= 16) {
                    int r0 = wbase + mt * 16 + (lid >> 2);
                    float bv0 = bos[cb];
                    float bv1 = (cb + 1 < 17) ? bos[cb + 1] : 0.f;
                    po[r0 * 20 + cb]           = acc[mt][j][0] + bv0;
                    po[r0 * 20 + cb + 1]       = acc[mt][j][1] + bv1;
                    po[(r0 + 8) * 20 + cb]     = acc[mt][j][2] + bv0;
                    po[(r0 + 8) * 20 + cb + 1] = acc[mt][j][3] + bv1;
                }
            }
    }
    __syncthreads();

    // ---------------- per-sample tail ----------------
    const float* myo = (const float*)(smem + AH) + rtid * 20;
    const float sigma = fmaxf(myo[0], 0.f);
    const float* wrgb = (const float*)(smem + SM_WRGB);
    const float* brg  = (const float*)(smem + SM_BRGB);
    float rgbv[3];
#pragma unroll
    for (int cc = 0; cc < 3; cc++) {
        float r = brg[cc];
#pragma unroll
        for (int k = 0; k < 16; k++) r = fmaf(myo[1 + k], wrgb[k * 3 + cc], r);
        rgbv[cc] = 1.0f / (1.0f + expf(-r));
    }

    const float dtv   = g_dt;
    const float alpha = 1.0f - expf(-sigma * dtv);
    const float q     = (1.0f - alpha) + 1e-10f;

    float p = q;
#pragma unroll
    for (int d = 1; d < 32; d <<= 1) {
        float u = __shfl_up_sync(0xffffffffu, p, d);
        if (lid >= d) p *= u;
    }
    __shared__ float wtot[RAYS_PER_CTA][4];
    if (lid == 31) wtot[rayi][wray] = p;
    __syncthreads();
    float pre = 1.0f;
    for (int w = 0; w < wray; w++) pre *= wtot[rayi][w];
    float excl = __shfl_up_sync(0xffffffffu, p, 1);
    if (lid == 0) excl = 1.0f;
    const float T    = pre * excl;
    const float incl = pre * p;
    const float wgt  = (T > 1e-4f) ? (T * alpha) : 0.f;

    float v0 = wgt * rgbv[0], v1 = wgt * rgbv[1], v2 = wgt * rgbv[2];
#pragma unroll
    for (int off = 16; off > 0; off >>= 1) {
        v0 += __shfl_down_sync(0xffffffffu, v0, off);
        v1 += __shfl_down_sync(0xffffffffu, v1, off);
        v2 += __shfl_down_sync(0xffffffffu, v2, off);
    }
    __shared__ float redc[RAYS_PER_CTA][4][3];
    if (lid == 0) { redc[rayi][wray][0] = v0; redc[rayi][wray][1] = v1; redc[rayi][wray][2] = v2; }
    if (rtid == SS - 1) out[3 * n + ray] = incl;
    __syncthreads();
    if (rtid == 0) {
        out[ray * 3 + 0] = redc[rayi][0][0] + redc[rayi][1][0] + redc[rayi][2][0] + redc[rayi][3][0];
        out[ray * 3 + 1] = redc[rayi][0][1] + redc[rayi][1][1] + redc[rayi][2][1] + redc[rayi][3][1];
        out[ray * 3 + 2] = redc[rayi][0][2] + redc[rayi][1][2] + redc[rayi][2][2] + redc[rayi][3][2];
    }
}

extern "C" void kernel_launch(void* const* d_in, const int* in_sizes, int n_in,
                              void* d_out, int out_size) {
    const float* ox   = (const float*)d_in[0];
    const float* oy   = (const float*)d_in[1];
    const float* oz   = (const float*)d_in[2];
    const float* dxv  = (const float*)d_in[3];
    const float* dyv  = (const float*)d_in[4];
    const float* dzv  = (const float*)d_in[5];
    const float* tmin = (const float*)d_in[6];
    const float* tmax = (const float*)d_in[7];
    const float* W1   = (const float*)d_in[8];
    const float* b1   = (const float*)d_in[9];
    const float* W2   = (const float*)d_in[10];
    const float* b2   = (const float*)d_in[11];
    const float* Wo   = (const float*)d_in[12];
    const float* bo   = (const float*)d_in[13];
    const float* Wrgb = (const float*)d_in[14];
    const float* brgb = (const float*)d_in[15];
    float* out = (float*)d_out;
    const int n = in_sizes[0];

    cudaFuncSetAttribute(nerf_mma_kernel, cudaFuncAttributeMaxDynamicSharedMemorySize, SM_TOTAL);

    prep_kernel<<<1, 256>>>(tmin, tmax, W1, W2, Wo, n);
    nerf_mma_kernel<<<n / RAYS_PER_CTA, TPB, SM_TOTAL>>>(
        ox, oy, oz, dxv, dyv, dzv, tmin, tmax,
        b1, b2, bo, Wrgb, brgb, out, n);
}